// round 1
// baseline (speedup 1.0000x reference)
#include <cuda_runtime.h>

// AvgPool over last 4 dims of [B=2, C=16, 32,32,32,32], k=s=2, pad=0.
// Input strides (floats): d4:1, d3:32, d2:1024, d1:32768, bc:1048576
// Output [2,16,16,16,16,16] strides: o4:1, o3:16, o2:256, o1:4096, bc:65536
//
// One thread -> 2 outputs adjacent in o4. Per thread: 8 float4 loads
// (one per (d1,d2,d3) in {0,1}^3, each spanning 4 consecutive d4 floats),
// one float2 store. Fully coalesced both directions.

__global__ __launch_bounds__(256) void avgpool4d_kernel(
    const float* __restrict__ in, float* __restrict__ out)
{
    const int tid = blockIdx.x * blockDim.x + threadIdx.x;
    // total output pairs = 2*16*16*16*16*8 = 1,048,576 (exact grid, no guard needed
    // when launched with 4096 blocks x 256; keep guard for safety)
    if (tid >= 1048576) return;

    const int t4p = tid & 7;           // pair index along o4 (0..7)
    int r = tid >> 3;
    const int o3 = r & 15;  r >>= 4;
    const int o2 = r & 15;  r >>= 4;
    const int o1 = r & 15;  r >>= 4;
    const int bc = r;                  // 0..31

    // input base (floats), 16B aligned: 4*t4p + 64*o3 + 2048*o2 + 65536*o1 + 1048576*bc
    const long base = (long)bc * 1048576 + (long)(o1 << 1) * 32768
                    + (long)(o2 << 1) * 1024 + (long)(o3 << 1) * 32 + (t4p << 2);

    const float4* __restrict__ p = reinterpret_cast<const float4*>(in + base);
    // float4 index strides: d3 -> 32/4 = 8, d2 -> 1024/4 = 256, d1 -> 32768/4 = 8192
    float4 v0 = p[0];
    float4 v1 = p[8];
    float4 v2 = p[256];
    float4 v3 = p[256 + 8];
    float4 v4 = p[8192];
    float4 v5 = p[8192 + 8];
    float4 v6 = p[8192 + 256];
    float4 v7 = p[8192 + 256 + 8];

    float s0 = ((v0.x + v0.y) + (v1.x + v1.y))
             + ((v2.x + v2.y) + (v3.x + v3.y))
             + ((v4.x + v4.y) + (v5.x + v5.y))
             + ((v6.x + v6.y) + (v7.x + v7.y));
    float s1 = ((v0.z + v0.w) + (v1.z + v1.w))
             + ((v2.z + v2.w) + (v3.z + v3.w))
             + ((v4.z + v4.w) + (v5.z + v5.w))
             + ((v6.z + v6.w) + (v7.z + v7.w));

    const float inv = 1.0f / 16.0f;
    float2 o;
    o.x = s0 * inv;
    o.y = s1 * inv;

    // output offset (floats): 2*t4p + 16*o3 + 256*o2 + 4096*o1 + 65536*bc
    const long oofs = (long)bc * 65536 + (long)o1 * 4096 + (long)o2 * 256
                    + (long)o3 * 16 + (t4p << 1);
    *reinterpret_cast<float2*>(out + oofs) = o;
}

extern "C" void kernel_launch(void* const* d_in, const int* in_sizes, int n_in,
                              void* d_out, int out_size)
{
    const float* in = (const float*)d_in[0];
    float* out = (float*)d_out;
    // out_size = 2,097,152; pairs = 1,048,576
    const int pairs = out_size >> 1;
    const int block = 256;
    const int grid = (pairs + block - 1) / block;   // 4096
    avgpool4d_kernel<<<grid, block>>>(in, out);
}